// round 3
// baseline (speedup 1.0000x reference)
#include <cuda_runtime.h>

// HadamardTransform: y[b,:,h,w] = (H_1024 @ pad(x[b,:,h,w]))[0:768] / 32
// FWHT-1024 per pixel. Two register passes (bits 5-9, then bits 0-4) with an
// smem transpose between them — no shuffles. 16 pixels/CTA, 512 threads,
// 2 CTAs/SM for phase overlap.

#define DIMC        768
#define TILE        16          // pixels per CTA
#define THREADS     512
#define PSTR        17          // smem row stride (floats)
#define PIX_PER_IMG 3136        // 56*56
#define TILES_PER_IMG 196       // 3136/16

__global__ __launch_bounds__(THREADS, 2)
void fwht1024_kernel(const float* __restrict__ x, float* __restrict__ y) {
    extern __shared__ float s[];   // [1024][17] floats = 69632 B

    const int tid = threadIdx.x;
    const int T   = blockIdx.x;
    const int b   = T / TILES_PER_IMG;
    const int p0  = (T % TILES_PER_IMG) * TILE;
    const size_t base = (size_t)b * DIMC * PIX_PER_IMG + p0;

    // ---- Phase 1: coalesced float4 load of [768 x 16] tile into smem ----
    // 768 rows * 4 float4/row = 3072 float4; 6 per thread.
    #pragma unroll
    for (int it = 0; it < 6; it++) {
        int f = it * THREADS + tid;      // 0..3071
        int c = f >> 2;                  // channel row
        int q = f & 3;                   // float4 index within 16 pixels
        float4 v = *(const float4*)(x + base + (size_t)c * PIX_PER_IMG + q * 4);
        float* sr = s + c * PSTR + q * 4;
        sr[0] = v.x; sr[1] = v.y; sr[2] = v.z; sr[3] = v.w;
    }
    __syncthreads();

    const int p = tid & 15;        // pixel within tile
    const int g = tid >> 4;        // 0..31 : fixed low-5-bits group

    // ---- Pass 1: butterfly over channel bits 5..9 ----
    // Thread owns channels c = j*32 + g, j = 0..31 (j >= 24 are zero pad).
    {
        float w[32];
        #pragma unroll
        for (int j = 0; j < 24; j++)
            w[j] = s[(j * 32 + g) * PSTR + p];
        #pragma unroll
        for (int j = 24; j < 32; j++)
            w[j] = 0.0f;

        #pragma unroll
        for (int st = 0; st < 5; st++) {
            const int m = 1 << st;
            #pragma unroll
            for (int j = 0; j < 32; j++) {
                if (!(j & m)) {
                    float a = w[j], c2 = w[j + m];
                    w[j]     = a + c2;
                    w[j + m] = a - c2;
                }
            }
        }

        #pragma unroll
        for (int j = 0; j < 32; j++)
            s[(j * 32 + g) * PSTR + p] = w[j];
    }
    __syncthreads();

    // ---- Pass 2: butterfly over channel bits 0..4 ----
    // Thread owns channels c = g*32 + j. Only g < 24 produce outputs < 768.
    if (g < 24) {
        float w[32];
        #pragma unroll
        for (int j = 0; j < 32; j++)
            w[j] = s[(g * 32 + j) * PSTR + p];

        #pragma unroll
        for (int st = 0; st < 5; st++) {
            const int m = 1 << st;
            #pragma unroll
            for (int j = 0; j < 32; j++) {
                if (!(j & m)) {
                    float a = w[j], c2 = w[j + m];
                    w[j]     = a + c2;
                    w[j + m] = a - c2;
                }
            }
        }

        const float scale = 1.0f / 32.0f;
        #pragma unroll
        for (int j = 0; j < 32; j++)
            s[(g * 32 + j) * PSTR + p] = w[j] * scale;
    }
    __syncthreads();

    // ---- Phase 4: coalesced float4 store of first 768 channels ----
    #pragma unroll
    for (int it = 0; it < 6; it++) {
        int f = it * THREADS + tid;
        int c = f >> 2;
        int q = f & 3;
        const float* sr = s + c * PSTR + q * 4;
        float4 v4 = make_float4(sr[0], sr[1], sr[2], sr[3]);
        *(float4*)(y + base + (size_t)c * PIX_PER_IMG + q * 4) = v4;
    }
}

extern "C" void kernel_launch(void* const* d_in, const int* in_sizes, int n_in,
                              void* d_out, int out_size) {
    (void)in_sizes; (void)n_in; (void)out_size;
    const float* x = (const float*)d_in[0];
    float* y = (float*)d_out;

    const int smem_bytes = 1024 * PSTR * sizeof(float);   // 69632
    cudaFuncSetAttribute(fwht1024_kernel,
                         cudaFuncAttributeMaxDynamicSharedMemorySize, smem_bytes);

    const int grid = 16 * TILES_PER_IMG;   // 3136 tiles
    fwht1024_kernel<<<grid, THREADS, smem_bytes>>>(x, y);
}

// round 4
// speedup vs baseline: 1.5940x; 1.5940x over previous
#include <cuda_runtime.h>

// HadamardTransform: y[b,:,h,w] = (H_1024 @ pad(x[b,:,h,w]))[0:768] / 32
// FWHT-1024 per pixel as (H32 over bits5-9) then (H32 over bits0-4).
// Pass 1 reads gmem directly; pass 2 writes gmem directly; single smem
// transpose of only the 768 needed intermediates in between. One barrier.

#define DIMC          768
#define TILE          16          // pixels per CTA
#define THREADS       512
#define PSTR          17          // smem row stride (floats), conflict-free
#define PIX_PER_IMG   3136        // 56*56
#define TILES_PER_IMG 196         // 3136/16

__global__ __launch_bounds__(THREADS, 2)
void fwht1024_kernel(const float* __restrict__ x, float* __restrict__ y) {
    extern __shared__ float s[];   // [768][17] floats = 52224 B

    const int tid = threadIdx.x;
    const int T   = blockIdx.x;
    const int b   = T / TILES_PER_IMG;
    const int p0  = (T % TILES_PER_IMG) * TILE;
    const size_t base = (size_t)b * DIMC * PIX_PER_IMG + p0;

    const int p = tid & 15;        // pixel within tile
    const int g = tid >> 4;        // 0..31

    // ---- Pass 1: butterfly over channel bits 5..9 ----
    // Thread owns channels c = j*32 + g for its pixel p.
    // j = 0..23 are real channels (c < 768); j >= 24 are zero padding.
    {
        float w[32];
        #pragma unroll
        for (int j = 0; j < 24; j++)
            w[j] = __ldg(x + base + (size_t)(j * 32 + g) * PIX_PER_IMG + p);
        #pragma unroll
        for (int j = 24; j < 32; j++)
            w[j] = 0.0f;

        #pragma unroll
        for (int st = 0; st < 5; st++) {
            const int m = 1 << st;
            #pragma unroll
            for (int j = 0; j < 32; j++) {
                if (!(j & m)) {
                    float a = w[j], c2 = w[j + m];
                    w[j]     = a + c2;
                    w[j + m] = a - c2;
                }
            }
        }

        // w[j] = t[k_hi=j, c_lo=g]. Outputs keep only k_hi < 24, so
        // intermediates with j >= 24 are never read — skip storing them.
        #pragma unroll
        for (int j = 0; j < 24; j++)
            s[(j * 32 + g) * PSTR + p] = w[j];
    }
    __syncthreads();

    // ---- Pass 2: butterfly over channel bits 0..4, direct gmem store ----
    // Thread (g < 24) produces output channels c = g*32 + j for pixel p.
    if (g < 24) {
        float w[32];
        #pragma unroll
        for (int j = 0; j < 32; j++)
            w[j] = s[(g * 32 + j) * PSTR + p];

        #pragma unroll
        for (int st = 0; st < 5; st++) {
            const int m = 1 << st;
            #pragma unroll
            for (int j = 0; j < 32; j++) {
                if (!(j & m)) {
                    float a = w[j], c2 = w[j + m];
                    w[j]     = a + c2;
                    w[j + m] = a - c2;
                }
            }
        }

        const float scale = 1.0f / 32.0f;
        #pragma unroll
        for (int j = 0; j < 32; j++)
            y[base + (size_t)(g * 32 + j) * PIX_PER_IMG + p] = w[j] * scale;
    }
}

extern "C" void kernel_launch(void* const* d_in, const int* in_sizes, int n_in,
                              void* d_out, int out_size) {
    (void)in_sizes; (void)n_in; (void)out_size;
    const float* x = (const float*)d_in[0];
    float* y = (float*)d_out;

    const int smem_bytes = DIMC * PSTR * sizeof(float);   // 52224
    cudaFuncSetAttribute(fwht1024_kernel,
                         cudaFuncAttributeMaxDynamicSharedMemorySize, smem_bytes);

    const int grid = 16 * TILES_PER_IMG;   // 3136 tiles
    fwht1024_kernel<<<grid, THREADS, smem_bytes>>>(x, y);
}

// round 5
// speedup vs baseline: 1.6669x; 1.0457x over previous
#include <cuda_runtime.h>
#include <cstdint>

// HadamardTransform: y[b,:,h,w] = (H_1024 @ pad(x[b,:,h,w]))[0:768] / 32
// FWHT-1024 per pixel, two register passes over channel bits (5-9 then 0-4),
// packed f32x2 math (2 pixels per thread), 64-bit gmem/smem ops throughout.

#define DIMC          768
#define TILE          16          // pixels per CTA
#define THREADS       256
#define PIX_PER_IMG   3136        // 56*56
#define TILES_PER_IMG 196         // 3136/16

// ---- packed f32x2 ops (sm_103a) ----
__device__ __forceinline__ uint64_t addx2(uint64_t a, uint64_t b) {
    uint64_t d; asm("add.rn.f32x2 %0, %1, %2;" : "=l"(d) : "l"(a), "l"(b)); return d;
}
__device__ __forceinline__ uint64_t subx2(uint64_t a, uint64_t b) {
    // a - b  ==  fma(b, -1.0x2, a)
    const uint64_t NEG1 = 0xBF800000BF800000ULL;
    uint64_t d; asm("fma.rn.f32x2 %0, %1, %2, %3;" : "=l"(d) : "l"(b), "l"(NEG1), "l"(a)); return d;
}
__device__ __forceinline__ uint64_t mulx2(uint64_t a, uint64_t b) {
    uint64_t d; asm("mul.rn.f32x2 %0, %1, %2;" : "=l"(d) : "l"(a), "l"(b)); return d;
}

// smem layout (float2 units): row r (0..767) at (r + (r>>5))*8 + p2.
// The +row>>5 per-32-row pad makes BOTH passes' 16-lane LDS/STS.64 phases
// hit disjoint bank halves (32-row stride = 528 words == 16 mod 32).
//   pass1 row = j*32+g  ->  idx = (j*33 + g)*8 + p2
//   pass2 row = g*32+j  ->  idx = (g*33 + j)*8 + p2

__global__ __launch_bounds__(THREADS, 3)
void fwht1024_kernel(const float* __restrict__ x, float* __restrict__ y) {
    extern __shared__ uint64_t s[];   // 792*8 = 6336 u64 = 50688 B

    const int tid = threadIdx.x;
    const int T   = blockIdx.x;
    const int b   = T / TILES_PER_IMG;
    const int p0  = (T % TILES_PER_IMG) * TILE;
    const size_t base = (size_t)b * DIMC * PIX_PER_IMG + p0;

    const int p2 = tid & 7;        // pixel pair -> pixels 2*p2, 2*p2+1
    const int g  = tid >> 3;       // 0..31

    // ---- Pass 1: butterfly over channel bits 5..9, gmem -> smem ----
    {
        uint64_t w[32];
        #pragma unroll
        for (int j = 0; j < 24; j++) {
            const float2 v = *(const float2*)(x + base +
                               (size_t)(j * 32 + g) * PIX_PER_IMG + 2 * p2);
            uint64_t u;
            asm("mov.b64 %0, {%1, %2};" : "=l"(u) : "f"(v.x), "f"(v.y));
            w[j] = u;
        }
        #pragma unroll
        for (int j = 24; j < 32; j++)
            w[j] = 0ULL;

        #pragma unroll
        for (int st = 0; st < 5; st++) {
            const int m = 1 << st;
            #pragma unroll
            for (int j = 0; j < 32; j++) {
                if (!(j & m)) {
                    uint64_t a = w[j], c2 = w[j + m];
                    w[j]     = addx2(a, c2);
                    w[j + m] = subx2(a, c2);
                }
            }
        }

        // only intermediates with j < 24 are ever read (outputs keep k < 768)
        #pragma unroll
        for (int j = 0; j < 24; j++)
            s[(j * 33 + g) * 8 + p2] = w[j];
    }
    __syncthreads();

    // ---- Pass 2: butterfly over channel bits 0..4, smem -> gmem ----
    if (g < 24) {
        uint64_t w[32];
        #pragma unroll
        for (int j = 0; j < 32; j++)
            w[j] = s[(g * 33 + j) * 8 + p2];

        #pragma unroll
        for (int st = 0; st < 5; st++) {
            const int m = 1 << st;
            #pragma unroll
            for (int j = 0; j < 32; j++) {
                if (!(j & m)) {
                    uint64_t a = w[j], c2 = w[j + m];
                    w[j]     = addx2(a, c2);
                    w[j + m] = subx2(a, c2);
                }
            }
        }

        const uint64_t SCALE = 0x3D0000003D000000ULL;   // (1/32, 1/32)
        #pragma unroll
        for (int j = 0; j < 32; j++) {
            uint64_t r = mulx2(w[j], SCALE);
            float lo, hi;
            asm("mov.b64 {%0, %1}, %2;" : "=f"(lo), "=f"(hi) : "l"(r));
            *(float2*)(y + base + (size_t)(g * 32 + j) * PIX_PER_IMG + 2 * p2)
                = make_float2(lo, hi);
        }
    }
}

extern "C" void kernel_launch(void* const* d_in, const int* in_sizes, int n_in,
                              void* d_out, int out_size) {
    (void)in_sizes; (void)n_in; (void)out_size;
    const float* x = (const float*)d_in[0];
    float* y = (float*)d_out;

    const int smem_bytes = 792 * 8 * sizeof(uint64_t);   // 50688
    cudaFuncSetAttribute(fwht1024_kernel,
                         cudaFuncAttributeMaxDynamicSharedMemorySize, smem_bytes);

    const int grid = 16 * TILES_PER_IMG;   // 3136 tiles
    fwht1024_kernel<<<grid, THREADS, smem_bytes>>>(x, y);
}